// round 8
// baseline (speedup 1.0000x reference)
#include <cuda_runtime.h>
#include <math_constants.h>

// ChamferLoss via exact pruned nearest-neighbor search.
// 1) sort_kernel: bitonic-sort each point cloud by z (per batch), write float4
//    records with +/-1e30 sentinel pads.
// 2) nn_kernel: per query, outward two-pointer scan over z-sorted candidates
//    starting at the query's own rank. A side terminates when its CLAMPED
//    z-gap^2 >= best (exact bound; clamp handles rank-offset starts).
//    4 candidates per side per iteration (batched loads, ILP chains).
// d2 computed in direct diff form (no cancellation).

#define B_DIM  8
#define N_PTS  4096
#define PAD    4
#define NTOT   (N_PTS + 2 * PAD)
#define EPS    1e-8f
#define SORT_T 1024
#define NN_T   256

__device__ float4 g_sorted[2][B_DIM][NTOT];   // [arr: 0=x,1=y][b][PAD+i]

__global__ __launch_bounds__(SORT_T) void sort_kernel(
    const float* __restrict__ x1, const float* __restrict__ y1, float* out)
{
    __shared__ float skey[N_PTS];
    __shared__ int   sidx[N_PTS];

    const int arr = blockIdx.x;
    const int b   = blockIdx.y;
    const float* src = ((arr == 0) ? x1 : y1) + (size_t)b * N_PTS * 3;
    const int tid = threadIdx.x;

    if (arr == 0 && b == 0 && tid == 0) out[0] = 0.0f;

    for (int i = tid; i < N_PTS; i += SORT_T) {
        skey[i] = src[i * 3 + 2];
        sidx[i] = i;
    }
    __syncthreads();

    // bitonic sort ascending by z
    for (int k = 2; k <= N_PTS; k <<= 1) {
        for (int j = k >> 1; j > 0; j >>= 1) {
            for (int w = tid; w < N_PTS / 2; w += SORT_T) {
                const int i = ((w & ~(j - 1)) << 1) | (w & (j - 1));
                const int p = i + j;
                const bool up = ((i & k) == 0);
                const float ka = skey[i], kb = skey[p];
                if ((ka > kb) == up) {
                    skey[i] = kb; skey[p] = ka;
                    const int t = sidx[i]; sidx[i] = sidx[p]; sidx[p] = t;
                }
            }
            __syncthreads();
        }
    }

    // gather sorted records + sentinels
    float4* dst = g_sorted[arr][b];
    for (int i = tid; i < N_PTS; i += SORT_T) {
        const int o = sidx[i];
        dst[PAD + i] = make_float4(src[o * 3 + 0], src[o * 3 + 1], src[o * 3 + 2], 0.0f);
    }
    if (tid < PAD) {
        dst[tid]                 = make_float4(0.0f, 0.0f, -1e30f, 0.0f);
        dst[PAD + N_PTS + tid]   = make_float4(0.0f, 0.0f,  1e30f, 0.0f);
    }
}

__device__ __forceinline__ float d2f(float4 q, float4 c) {
    const float dx = q.x - c.x;
    const float dy = q.y - c.y;
    const float dz = q.z - c.z;
    return fmaf(dx, dx, fmaf(dy, dy, dz * dz));
}

__global__ __launch_bounds__(NN_T) void nn_kernel(float* out, float scale)
{
    __shared__ float wsum[NN_T / 32];

    const int dir = blockIdx.z;           // 0: x->y, 1: y->x
    const int b   = blockIdx.y;
    const float4* __restrict__ Qa = g_sorted[dir][b];
    const float4* __restrict__ Ca = g_sorted[1 - dir][b];

    const int q = blockIdx.x * NN_T + threadIdx.x;
    const float4 me = Qa[PAD + q];

    float best = CUDART_INF_F;
    int L = q - 1;
    int R = q;

    for (;;) {
        const float zl = Ca[PAD + L].z;
        const float zr = Ca[PAD + R].z;
        const float gl = fmaxf(me.z - zl, 0.0f);   // clamp: rank-offset start
        const float gr = fmaxf(zr - me.z, 0.0f);
        const bool advL = (gl * gl < best);
        const bool advR = (gr * gr < best);
        if (!advL && !advR) break;
        if (advL) {
            const float4 c0 = Ca[PAD + L];
            const float4 c1 = Ca[PAD + L - 1];
            const float4 c2 = Ca[PAD + L - 2];
            const float4 c3 = Ca[PAD + L - 3];
            const float a0 = fminf(d2f(me, c0), d2f(me, c1));
            const float a1 = fminf(d2f(me, c2), d2f(me, c3));
            best = fminf(best, fminf(a0, a1));
            L -= 4;
        }
        if (advR) {
            const float4 c0 = Ca[PAD + R];
            const float4 c1 = Ca[PAD + R + 1];
            const float4 c2 = Ca[PAD + R + 2];
            const float4 c3 = Ca[PAD + R + 3];
            const float a0 = fminf(d2f(me, c0), d2f(me, c1));
            const float a1 = fminf(d2f(me, c2), d2f(me, c3));
            best = fminf(best, fminf(a0, a1));
            R += 4;
        }
    }

    float v = sqrtf(fmaxf(best, 0.0f) + EPS);

    #pragma unroll
    for (int off = 16; off > 0; off >>= 1)
        v += __shfl_xor_sync(0xFFFFFFFFu, v, off);

    const int u = threadIdx.x & 31;
    const int w = threadIdx.x >> 5;
    if (u == 0) wsum[w] = v;
    __syncthreads();
    if (threadIdx.x == 0) {
        float t = 0.0f;
        #pragma unroll
        for (int ww = 0; ww < NN_T / 32; ++ww) t += wsum[ww];
        atomicAdd(out, t * scale);
    }
}

extern "C" void kernel_launch(void* const* d_in, const int* in_sizes, int n_in,
                              void* d_out, int out_size)
{
    const float* x1 = (const float*)d_in[0];
    const float* y1 = (const float*)d_in[1];
    float* out = (float*)d_out;

    sort_kernel<<<dim3(2, B_DIM), SORT_T>>>(x1, y1, out);

    const float scale = 1.0f / (float)(B_DIM * N_PTS);
    nn_kernel<<<dim3(N_PTS / NN_T, B_DIM, 2), NN_T>>>(out, scale);
}

// round 9
// speedup vs baseline: 1.3026x; 1.3026x over previous
#include <cuda_runtime.h>
#include <math_constants.h>

// ChamferLoss via bucketed counting sort on z + exact two-phase pruned NN scan.
// sort_kernel (grid 2x8): histogram 512 z-buckets -> smem prefix scan -> scatter
//   records (x,y,z,|c|^2) into bucket-contiguous order.
// nn_kernel: per query q (taken from the sorted array of its own side):
//   phase 1: scan own bucket +/-rad (rad doubles until >=8 candidates) as a
//            PLAIN COUNTED LOOP -> best1.
//   phase 2: r = sqrt(best1); scan remaining buckets covering [z-r, z+r]
//            (provably sufficient; floor-monotone bucketing) -> exact best.
// No termination checks inside hot loops -> no load->branch serial chains.

#define B_DIM  8
#define N_PTS  4096
#define NB     512
#define ZMIN   (-4.0f)
#define ZSCALE 64.0f          // 512 buckets over [-4, 4]
#define EPS    1e-8f
#define SORT_T 512
#define NN_T   256

__device__ float4 g_sorted[2][B_DIM][N_PTS];   // (x, y, z, x^2+y^2+z^2)
__device__ int    g_off[2][B_DIM][NB + 1];     // exclusive bucket offsets

__device__ __forceinline__ int zbucket(float z) {
    int bk = (int)floorf((z - ZMIN) * ZSCALE);
    return min(NB - 1, max(0, bk));
}

__global__ __launch_bounds__(SORT_T) void sort_kernel(
    const float* __restrict__ x1, const float* __restrict__ y1, float* out)
{
    __shared__ int hist[NB];
    __shared__ int offs[NB];
    __shared__ int scan_tmp[NB];

    const int arr = blockIdx.x;
    const int b   = blockIdx.y;
    const float* src = ((arr == 0) ? x1 : y1) + (size_t)b * N_PTS * 3;
    const int tid = threadIdx.x;

    if (arr == 0 && b == 0 && tid == 0) out[0] = 0.0f;

    for (int i = tid; i < NB; i += SORT_T) hist[i] = 0;
    __syncthreads();

    for (int i = tid; i < N_PTS; i += SORT_T)
        atomicAdd(&hist[zbucket(src[i * 3 + 2])], 1);
    __syncthreads();

    // exclusive Hillis-Steele scan of hist -> offs (512 elements, 512 threads)
    if (tid < NB) scan_tmp[tid] = hist[tid];
    __syncthreads();
    for (int d = 1; d < NB; d <<= 1) {
        int v = 0;
        if (tid < NB && tid >= d) v = scan_tmp[tid - d];
        __syncthreads();
        if (tid < NB) scan_tmp[tid] += v;
        __syncthreads();
    }
    if (tid < NB) offs[tid] = scan_tmp[tid] - hist[tid];   // inclusive -> exclusive
    __syncthreads();

    // publish offsets
    if (tid < NB) g_off[arr][b][tid] = offs[tid];
    if (tid == 0) g_off[arr][b][NB] = N_PTS;

    // reuse hist as running counters
    for (int i = tid; i < NB; i += SORT_T) hist[i] = 0;
    __syncthreads();

    float4* dst = g_sorted[arr][b];
    for (int i = tid; i < N_PTS; i += SORT_T) {
        const float x = src[i * 3 + 0];
        const float y = src[i * 3 + 1];
        const float z = src[i * 3 + 2];
        const int bk  = zbucket(z);
        const int pos = offs[bk] + atomicAdd(&hist[bk], 1);
        dst[pos] = make_float4(x, y, z, fmaf(x, x, fmaf(y, y, z * z)));
    }
}

__global__ __launch_bounds__(NN_T) void nn_kernel(float* out, float scale)
{
    __shared__ int soff[NB + 1];
    __shared__ float wsum[NN_T / 32];

    const int dir = blockIdx.z;            // 0: x->y, 1: y->x
    const int b   = blockIdx.y;
    const float4* __restrict__ Ca = g_sorted[1 - dir][b];
    const int* __restrict__ goff  = g_off[1 - dir][b];

    const int tid = threadIdx.x;
    for (int i = tid; i <= NB; i += NN_T) soff[i] = goff[i];
    __syncthreads();

    const int q = blockIdx.x * NN_T + tid;
    const float4 me = g_sorted[dir][b][q];
    const float nqx = -2.0f * me.x;
    const float nqy = -2.0f * me.y;
    const float nqz = -2.0f * me.z;
    const float qsq = me.w;

    const int b0 = zbucket(me.z);

    // phase 1: expanding window until >= 8 candidates (plain counted scan)
    int rad = 2, lo, hi, beg, end;
    for (;;) {
        lo = max(b0 - rad, 0);
        hi = min(b0 + rad, NB - 1);
        beg = soff[lo];
        end = soff[hi + 1];
        if (end - beg >= 8 || (lo == 0 && hi == NB - 1)) break;
        rad <<= 1;
    }

    float best = CUDART_INF_F;
    #pragma unroll 4
    for (int i = beg; i < end; ++i) {
        const float4 c = Ca[i];
        float t = fmaf(nqz, c.z, qsq + c.w);
        t = fmaf(nqy, c.y, t);
        t = fmaf(nqx, c.x, t);
        best = fminf(best, t);
    }

    // phase 2: provably sufficient range from best1
    const float r = sqrtf(fmaxf(best, 0.0f));
    const int Lb = zbucket(me.z - r);
    const int Rb = zbucket(me.z + r);
    const int Lbeg = soff[max(Lb, 0)];
    const int Rend = soff[min(Rb, NB - 1) + 1];

    #pragma unroll 4
    for (int i = Lbeg; i < beg; ++i) {
        const float4 c = Ca[i];
        float t = fmaf(nqz, c.z, qsq + c.w);
        t = fmaf(nqy, c.y, t);
        t = fmaf(nqx, c.x, t);
        best = fminf(best, t);
    }
    #pragma unroll 4
    for (int i = end; i < Rend; ++i) {
        const float4 c = Ca[i];
        float t = fmaf(nqz, c.z, qsq + c.w);
        t = fmaf(nqy, c.y, t);
        t = fmaf(nqx, c.x, t);
        best = fminf(best, t);
    }

    float v = sqrtf(fmaxf(best, 0.0f) + EPS);

    #pragma unroll
    for (int off = 16; off > 0; off >>= 1)
        v += __shfl_xor_sync(0xFFFFFFFFu, v, off);

    const int u = tid & 31;
    const int w = tid >> 5;
    if (u == 0) wsum[w] = v;
    __syncthreads();
    if (tid == 0) {
        float t = 0.0f;
        #pragma unroll
        for (int ww = 0; ww < NN_T / 32; ++ww) t += wsum[ww];
        atomicAdd(out, t * scale);
    }
}

extern "C" void kernel_launch(void* const* d_in, const int* in_sizes, int n_in,
                              void* d_out, int out_size)
{
    const float* x1 = (const float*)d_in[0];
    const float* y1 = (const float*)d_in[1];
    float* out = (float*)d_out;

    sort_kernel<<<dim3(2, B_DIM), SORT_T>>>(x1, y1, out);

    const float scale = 1.0f / (float)(B_DIM * N_PTS);
    nn_kernel<<<dim3(N_PTS / NN_T, B_DIM, 2), NN_T>>>(out, scale);
}

// round 10
// speedup vs baseline: 1.3085x; 1.0045x over previous
#include <cuda_runtime.h>
#include <math_constants.h>

// ChamferLoss: counting-sort by z + exact pruned NN with WARP-UNIFORM scans.
// All hot loops: every lane iterates the same j -> broadcast LDG.128, L1-resident.
// phase 1: warp rank-window [qw-P1, qw+32+P1) -> best1 (upper bound on NN dist).
// phase 2: warp z-window [min(z-r), max(z+r)] -> bucket rank range -> scan flanks.
// Exact: true NN satisfies |zc - zq| <= d <= r, covered by the warp window.

#define B_DIM  8
#define N_PTS  4096
#define NB     512
#define ZMIN   (-4.0f)
#define ZSCALE 64.0f
#define EPS    1e-8f
#define SORT_T 1024
#define NN_T   256
#define P1     64

__device__ float4 g_sorted[2][B_DIM][N_PTS];   // (x, y, z, |c|^2)
__device__ int    g_off[2][B_DIM][NB + 1];

__device__ __forceinline__ int zbucket(float z) {
    int bk = (int)floorf((z - ZMIN) * ZSCALE);
    return min(NB - 1, max(0, bk));
}

__global__ __launch_bounds__(SORT_T) void sort_kernel(
    const float* __restrict__ x1, const float* __restrict__ y1, float* out)
{
    __shared__ int hist[NB];
    __shared__ int offs[NB];
    __shared__ int scan_tmp[NB];

    const int arr = blockIdx.x;
    const int b   = blockIdx.y;
    const float* src = ((arr == 0) ? x1 : y1) + (size_t)b * N_PTS * 3;
    const int tid = threadIdx.x;

    if (arr == 0 && b == 0 && tid == 0) out[0] = 0.0f;

    for (int i = tid; i < NB; i += SORT_T) hist[i] = 0;
    __syncthreads();

    for (int i = tid; i < N_PTS; i += SORT_T)
        atomicAdd(&hist[zbucket(src[i * 3 + 2])], 1);
    __syncthreads();

    // Hillis-Steele inclusive scan (512 elems), then convert to exclusive
    if (tid < NB) scan_tmp[tid] = hist[tid];
    __syncthreads();
    for (int d = 1; d < NB; d <<= 1) {
        int v = 0;
        if (tid < NB && tid >= d) v = scan_tmp[tid - d];
        __syncthreads();
        if (tid < NB) scan_tmp[tid] += v;
        __syncthreads();
    }
    if (tid < NB) offs[tid] = scan_tmp[tid] - hist[tid];
    __syncthreads();

    if (tid < NB) g_off[arr][b][tid] = offs[tid];
    if (tid == 0) g_off[arr][b][NB] = N_PTS;

    for (int i = tid; i < NB; i += SORT_T) hist[i] = 0;   // reuse as counters
    __syncthreads();

    float4* dst = g_sorted[arr][b];
    for (int i = tid; i < N_PTS; i += SORT_T) {
        const float x = src[i * 3 + 0];
        const float y = src[i * 3 + 1];
        const float z = src[i * 3 + 2];
        const int bk  = zbucket(z);
        const int pos = offs[bk] + atomicAdd(&hist[bk], 1);
        dst[pos] = make_float4(x, y, z, fmaf(x, x, fmaf(y, y, z * z)));
    }
}

__global__ __launch_bounds__(NN_T) void nn_kernel(float* out, float scale)
{
    __shared__ float wsum[NN_T / 32];

    const int dir = blockIdx.z;            // 0: x->y, 1: y->x
    const int b   = blockIdx.y;
    const float4* __restrict__ Ca = g_sorted[1 - dir][b];
    const int* __restrict__ coff  = g_off[1 - dir][b];

    const int tid = threadIdx.x;
    const int u   = tid & 31;
    const int w   = tid >> 5;
    const int qw  = blockIdx.x * NN_T + w * 32;   // warp's base rank (uniform)
    const int q   = qw + u;

    const float4 me = g_sorted[dir][b][q];
    const float nqx = -2.0f * me.x;
    const float nqy = -2.0f * me.y;
    const float nqz = -2.0f * me.z;
    const float qsq = me.w;

    // phase 1: warp-uniform rank window
    const int cbeg1 = max(qw - P1, 0);
    const int cend1 = min(qw + 32 + P1, N_PTS);

    float best = CUDART_INF_F;
    #pragma unroll 4
    for (int j = cbeg1; j < cend1; ++j) {
        const float4 c = Ca[j];
        float t = fmaf(nqz, c.z, qsq + c.w);
        t = fmaf(nqy, c.y, t);
        t = fmaf(nqx, c.x, t);
        best = fminf(best, t);
    }

    // warp-uniform z window from per-lane radii (inflated for fp rounding)
    const float r = sqrtf(fmaxf(best, 0.0f)) * 1.0001f + 1e-4f;
    float wlo = me.z - r;
    float whi = me.z + r;
    #pragma unroll
    for (int off = 16; off > 0; off >>= 1) {
        wlo = fminf(wlo, __shfl_xor_sync(0xFFFFFFFFu, wlo, off));
        whi = fmaxf(whi, __shfl_xor_sync(0xFFFFFFFFu, whi, off));
    }

    const int Lb = zbucket(wlo);
    const int Rb = zbucket(whi);
    const int L  = min(coff[Lb], cbeg1);      // warp-uniform
    const int R  = max(coff[Rb + 1], cend1);

    // phase 2: flanks (warp-uniform counted loops)
    #pragma unroll 4
    for (int j = L; j < cbeg1; ++j) {
        const float4 c = Ca[j];
        float t = fmaf(nqz, c.z, qsq + c.w);
        t = fmaf(nqy, c.y, t);
        t = fmaf(nqx, c.x, t);
        best = fminf(best, t);
    }
    #pragma unroll 4
    for (int j = cend1; j < R; ++j) {
        const float4 c = Ca[j];
        float t = fmaf(nqz, c.z, qsq + c.w);
        t = fmaf(nqy, c.y, t);
        t = fmaf(nqx, c.x, t);
        best = fminf(best, t);
    }

    float v = sqrtf(fmaxf(best, 0.0f) + EPS);

    #pragma unroll
    for (int off = 16; off > 0; off >>= 1)
        v += __shfl_xor_sync(0xFFFFFFFFu, v, off);

    if (u == 0) wsum[w] = v;
    __syncthreads();
    if (tid == 0) {
        float t = 0.0f;
        #pragma unroll
        for (int ww = 0; ww < NN_T / 32; ++ww) t += wsum[ww];
        atomicAdd(out, t * scale);
    }
}

extern "C" void kernel_launch(void* const* d_in, const int* in_sizes, int n_in,
                              void* d_out, int out_size)
{
    const float* x1 = (const float*)d_in[0];
    const float* y1 = (const float*)d_in[1];
    float* out = (float*)d_out;

    sort_kernel<<<dim3(2, B_DIM), SORT_T>>>(x1, y1, out);

    const float scale = 1.0f / (float)(B_DIM * N_PTS);
    nn_kernel<<<dim3(N_PTS / NN_T, B_DIM, 2), NN_T>>>(out, scale);
}

// round 11
// speedup vs baseline: 3.6519x; 2.7908x over previous
#include <cuda_runtime.h>
#include <math_constants.h>

// ChamferLoss: counting-sort by z + exact pruned NN using the smem-tile engine.
// Stage A: dense scan of candidate ranks [Q0-128, Q0+384) from smem -> bound.
// Stage B: per-warp z-window [z-r, z+r] -> bucket->rank range; block-union
//          window streamed through 1024-candidate smem tiles; each warp scans
//          its own sub-range as warp-uniform counted segments (stage A excluded).
// All hot loops: LDS broadcast + FFMA, dense, counted. No gmem pointer-chasing.

#define B_DIM  8
#define N_PTS  4096
#define NB     512
#define ZMIN   (-4.0f)
#define ZSCALE 64.0f
#define EPS    1e-8f
#define SORT_T 1024
#define QPB    256         // queries per block (1 per thread)
#define APAD   128
#define AWIN   (QPB + 2 * APAD)   // 512 stage-A candidates
#define TILE_B 1024        // stage-B tile

__device__ float4 g_sorted[2][B_DIM][N_PTS];   // (x, y, z, |c|^2)
__device__ int    g_off[2][B_DIM][NB + 1];

__device__ __forceinline__ int zbucket(float z) {
    int bk = (int)floorf((z - ZMIN) * ZSCALE);
    return min(NB - 1, max(0, bk));
}

__global__ __launch_bounds__(SORT_T) void sort_kernel(
    const float* __restrict__ x1, const float* __restrict__ y1, float* out)
{
    __shared__ int hist[NB];
    __shared__ int offs[NB];
    __shared__ int scan_tmp[NB];

    const int arr = blockIdx.x;
    const int b   = blockIdx.y;
    const float* src = ((arr == 0) ? x1 : y1) + (size_t)b * N_PTS * 3;
    const int tid = threadIdx.x;

    if (arr == 0 && b == 0 && tid == 0) out[0] = 0.0f;

    for (int i = tid; i < NB; i += SORT_T) hist[i] = 0;
    __syncthreads();

    for (int i = tid; i < N_PTS; i += SORT_T)
        atomicAdd(&hist[zbucket(src[i * 3 + 2])], 1);
    __syncthreads();

    if (tid < NB) scan_tmp[tid] = hist[tid];
    __syncthreads();
    for (int d = 1; d < NB; d <<= 1) {
        int v = 0;
        if (tid < NB && tid >= d) v = scan_tmp[tid - d];
        __syncthreads();
        if (tid < NB) scan_tmp[tid] += v;
        __syncthreads();
    }
    if (tid < NB) offs[tid] = scan_tmp[tid] - hist[tid];
    __syncthreads();

    if (tid < NB) g_off[arr][b][tid] = offs[tid];
    if (tid == 0) g_off[arr][b][NB] = N_PTS;

    for (int i = tid; i < NB; i += SORT_T) hist[i] = 0;
    __syncthreads();

    float4* dst = g_sorted[arr][b];
    for (int i = tid; i < N_PTS; i += SORT_T) {
        const float x = src[i * 3 + 0];
        const float y = src[i * 3 + 1];
        const float z = src[i * 3 + 2];
        const int bk  = zbucket(z);
        const int pos = offs[bk] + atomicAdd(&hist[bk], 1);
        dst[pos] = make_float4(x, y, z, fmaf(x, x, fmaf(y, y, z * z)));
    }
}

__global__ __launch_bounds__(QPB) void nn_kernel(float* out, float scale)
{
    __shared__ float4 sC[TILE_B];      // 16KB candidate tile (stage A uses [0,AWIN))
    __shared__ int    soff[NB + 1];
    __shared__ int    swL[QPB / 32], swR[QPB / 32];
    __shared__ float  wsum[QPB / 32];

    const int dir = blockIdx.z;
    const int b   = blockIdx.y;
    const float4* __restrict__ Ca = g_sorted[1 - dir][b];
    const int* __restrict__ goff  = g_off[1 - dir][b];

    const int tid = threadIdx.x;
    const int u   = tid & 31;
    const int w   = tid >> 5;
    const int Q0  = blockIdx.x * QPB;

    for (int i = tid; i <= NB; i += QPB) soff[i] = goff[i];

    // ---- stage A: stage candidate ranks [A0, A1) into smem ----
    const int A0 = max(Q0 - APAD, 0);
    const int A1 = min(Q0 + QPB + APAD, N_PTS);
    const int an = A1 - A0;
    for (int i = tid; i < an; i += QPB) sC[i] = Ca[A0 + i];
    __syncthreads();

    const float4 me = g_sorted[dir][b][Q0 + tid];
    const float nqx = -2.0f * me.x;
    const float nqy = -2.0f * me.y;
    const float nqz = -2.0f * me.z;
    const float qsq = me.w;

    float m0 = CUDART_INF_F, m1 = CUDART_INF_F;
    float m2 = CUDART_INF_F, m3 = CUDART_INF_F;
    {
        int i = 0;
        for (; i + 4 <= an; i += 4) {
            const float4 c0 = sC[i + 0];
            const float4 c1 = sC[i + 1];
            const float4 c2 = sC[i + 2];
            const float4 c3 = sC[i + 3];
            float t0 = fmaf(nqz, c0.z, qsq + c0.w);
            float t1 = fmaf(nqz, c1.z, qsq + c1.w);
            float t2 = fmaf(nqz, c2.z, qsq + c2.w);
            float t3 = fmaf(nqz, c3.z, qsq + c3.w);
            t0 = fmaf(nqy, c0.y, t0); t1 = fmaf(nqy, c1.y, t1);
            t2 = fmaf(nqy, c2.y, t2); t3 = fmaf(nqy, c3.y, t3);
            t0 = fmaf(nqx, c0.x, t0); t1 = fmaf(nqx, c1.x, t1);
            t2 = fmaf(nqx, c2.x, t2); t3 = fmaf(nqx, c3.x, t3);
            m0 = fminf(m0, t0); m1 = fminf(m1, t1);
            m2 = fminf(m2, t2); m3 = fminf(m3, t3);
        }
        for (; i < an; ++i) {
            const float4 c = sC[i];
            float t = fmaf(nqz, c.z, qsq + c.w);
            t = fmaf(nqy, c.y, t);
            t = fmaf(nqx, c.x, t);
            m0 = fminf(m0, t);
        }
    }
    float best = fminf(fminf(m0, m1), fminf(m2, m3));

    // ---- warp window -> candidate rank range ----
    const float r = sqrtf(fmaxf(best, 0.0f)) * 1.001f + 1e-3f;
    float wlo = me.z - r;
    float whi = me.z + r;
    #pragma unroll
    for (int off = 16; off > 0; off >>= 1) {
        wlo = fminf(wlo, __shfl_xor_sync(0xFFFFFFFFu, wlo, off));
        whi = fmaxf(whi, __shfl_xor_sync(0xFFFFFFFFu, whi, off));
    }
    int wL = 0, wR = 0;
    if (u == 0) {
        wL = soff[zbucket(wlo)];
        wR = soff[zbucket(whi) + 1];
        swL[w] = wL;
        swR[w] = wR;
    }
    __syncthreads();

    // block union window
    int blockL = swL[0], blockR = swR[0];
    #pragma unroll
    for (int ww = 1; ww < QPB / 32; ++ww) {
        blockL = min(blockL, swL[ww]);
        blockR = max(blockR, swR[ww]);
    }
    wL = __shfl_sync(0xFFFFFFFFu, swL[w], 0);   // broadcast warp range
    wR = __shfl_sync(0xFFFFFFFFu, swR[w], 0);

    // ---- stage B: stream tiles over block union; warp scans its sub-range ----
    for (int tbase = blockL; tbase < blockR; tbase += TILE_B) {
        const int n = min(TILE_B, blockR - tbase);
        __syncthreads();
        for (int i = tid; i < n; i += QPB) sC[i] = Ca[tbase + i];
        __syncthreads();

        const int lo = max(wL, tbase);
        const int hi = min(wR, tbase + n);
        // segment 1: [lo, min(hi, A0))   segment 2: [max(lo, A1), hi)
        const int s1b = lo - tbase, s1e = min(hi, A0) - tbase;
        const int s2b = max(lo, A1) - tbase, s2e = hi - tbase;

        for (int j = s1b; j < s1e; ++j) {
            const float4 c = sC[j];
            float t = fmaf(nqz, c.z, qsq + c.w);
            t = fmaf(nqy, c.y, t);
            t = fmaf(nqx, c.x, t);
            best = fminf(best, t);
        }
        for (int j = s2b; j < s2e; ++j) {
            const float4 c = sC[j];
            float t = fmaf(nqz, c.z, qsq + c.w);
            t = fmaf(nqy, c.y, t);
            t = fmaf(nqx, c.x, t);
            best = fminf(best, t);
        }
    }

    float v = sqrtf(fmaxf(best, 0.0f) + EPS);

    #pragma unroll
    for (int off = 16; off > 0; off >>= 1)
        v += __shfl_xor_sync(0xFFFFFFFFu, v, off);

    if (u == 0) wsum[w] = v;
    __syncthreads();
    if (tid == 0) {
        float t = 0.0f;
        #pragma unroll
        for (int ww = 0; ww < QPB / 32; ++ww) t += wsum[ww];
        atomicAdd(out, t * scale);
    }
}

extern "C" void kernel_launch(void* const* d_in, const int* in_sizes, int n_in,
                              void* d_out, int out_size)
{
    const float* x1 = (const float*)d_in[0];
    const float* y1 = (const float*)d_in[1];
    float* out = (float*)d_out;

    sort_kernel<<<dim3(2, B_DIM), SORT_T>>>(x1, y1, out);

    const float scale = 1.0f / (float)(B_DIM * N_PTS);
    nn_kernel<<<dim3(N_PTS / QPB, B_DIM, 2), QPB>>>(out, scale);
}